// round 13
// baseline (speedup 1.0000x reference)
#include <cuda_runtime.h>
#include <cstdint>
#include <math.h>

#define B_    64
#define N_    4096
#define D_    128
#define E_    512
#define G_    592              // 148 SMs x 4 CTAs = exactly one wave
#define PRODB 4                // producer blocks per batch
#define TILE  32               // slots per tile (16KB)

// ---- device scratch (no allocations; 16B-aligned where float4-accessed) ----
// Replay-safe: g_qcnt / g_fin are cumulative monotonic counters; data arrays
// are rewritten with identical values each replay before being read.
__device__ __align__(16) float g_q  [B_*D_];
__device__ __align__(16) float g_qa [B_*D_];
__device__ float g_part_acc[(size_t)G_ * B_ * D_];   // ~19.4 MB
__device__ float g_part_s  [G_ * B_];
__device__ int   g_qcnt[B_];
__device__ int   g_fin;

__global__ void __launch_bounds__(256, 4)
fused_kernel(const float* __restrict__ kb,
             const float* __restrict__ vq,
             const int*   __restrict__ ion,
             const float* __restrict__ Wq,
             const float* __restrict__ bq,
             const float* __restrict__ Wa,
             const float* __restrict__ ba_p,
             float*       __restrict__ out)
{
    const int tid  = threadIdx.x;
    const int warp = tid >> 5, lane = tid & 31;
    const int bid  = blockIdx.x;

    // tile ring: 2 x 32 slots x 32 float4 (XOR-swizzled columns) = 32KB
    __shared__ __align__(16) float4 sbuf[2][TILE*32];
    __shared__ float    wbuf[2][TILE];
    __shared__ __align__(16) float sq[D_], sqa[D_];
    __shared__ __align__(16) float sacc[8][132];
    __shared__ float    ssum[8];
    __shared__ int      sP[B_ + 1];            // exclusive prefix of limits
    __shared__ unsigned suE, suO;              // uniform-batch bitmasks
    __shared__ float    sM, sba;
    __shared__ int      sticket;

    unsigned int sbase;
    asm("{ .reg .u64 t; cvta.to.shared.u64 t, %1; cvt.u32.u64 %0, t; }"
        : "=r"(sbase) : "l"(&sbuf[0][0]));

    // ---- meta: limits, prefix sum, uniform mask (warp 0); M bound (warp 1) ----
    if (warp == 0) {
        // int64 vs int32 decode: values in [0,4096); if int64 (LE) every odd
        // 32-bit word of the first 64 is 0. Detection reads stay in first
        // 256B; int64-mode reads go up to word 126 (<512B alloc).
        bool oz   = (ion[2*lane + 1] == 0);
        bool is64 = __all_sync(0xffffffffu, oz);
        int c0 = is64 ? ion[4*lane]     : ion[2*lane];
        int c1 = is64 ? ion[4*lane + 2] : ion[2*lane + 1];
        unsigned be = __ballot_sync(0xffffffffu, c0 == 0);
        unsigned bo = __ballot_sync(0xffffffffu, c1 == 0);
        int e0 = (c0 == 0) ? N_ : c0;          // cnt==0 -> uniform over all N
        int e1 = (c1 == 0) ? N_ : c1;
        int pair = e0 + e1, scan = pair;
        #pragma unroll
        for (int off = 1; off < 32; off <<= 1) {
            int t = __shfl_up_sync(0xffffffffu, scan, off);
            if (lane >= off) scan += t;
        }
        sP[2*lane]     = scan - pair;
        sP[2*lane + 1] = scan - e1;
        if (lane == 31) sP[B_] = scan;
        if (lane == 0) { suE = be; suO = bo; }
    } else if (warp == 1) {
        // M = max(ba + ||Wa||, 0) >= every logit (Cauchy-Schwarz)
        float t = 0.f;
        #pragma unroll
        for (int i = 0; i < 4; i++) { float wv = Wa[i*32 + lane]; t += wv*wv; }
        #pragma unroll
        for (int off = 16; off > 0; off >>= 1)
            t += __shfl_xor_sync(0xffffffffu, t, off);
        if (lane == 0) { float ba = *ba_p; sba = ba; sM = fmaxf(ba + sqrtf(t), 0.f); }
    }

    // ---- producers: blocks 0..255, 4 per batch, 32 outputs each ----
    if (bid < B_ * PRODB) {
        const int pb  = bid >> 2;
        const int qtr = bid & 3;
        const float4* v4 = (const float4*)(vq + (size_t)pb * E_);
        float4 v[4];
        #pragma unroll
        for (int j = 0; j < 4; j++) v[j] = v4[j*32 + lane];
        #pragma unroll
        for (int t = 0; t < 4; t++) {
            const int d = qtr * 32 + warp * 4 + t;
            const float4* w4 = (const float4*)(Wq + (size_t)d * E_);
            float a = 0.f;
            #pragma unroll
            for (int j = 0; j < 4; j++) {
                float4 y = w4[j*32 + lane];
                a += v[j].x*y.x + v[j].y*y.y + v[j].z*y.z + v[j].w*y.w;
            }
            #pragma unroll
            for (int off = 16; off > 0; off >>= 1)
                a += __shfl_xor_sync(0xffffffffu, a, off);
            if (lane == 0) {
                float qv = a + bq[d];
                g_q [pb*D_ + d] = qv;
                g_qa[pb*D_ + d] = qv * Wa[d];
            }
        }
        __syncthreads();
        __threadfence();
        if (tid == 0) atomicAdd(&g_qcnt[pb], 1);
    }
    __syncthreads();            // publish sP / sM / sba / masks

    const int W = sP[B_];
    const float M  = sM;
    const float ba = sba;

    // ---- balanced contiguous global-slot range for this block ----
    int g  = (int)((long long)bid       * W / G_);
    const int hi = (int)((long long)(bid + 1) * W / G_);
    int b = 0;

    // issue tile T into buf BUFI: 1024 float4, 4 per thread, coalesced
    // globally; smem column XOR-swizzled by (row&7). Rows clamp to n1-1
    // (clamped rows get w=0 in phase 1 -> contribute nothing).
    #define ISSUE_TILE(T, BUFI) do {                                         \
        const int _ts = n0 + (T) * TILE;                                     \
        _Pragma("unroll")                                                    \
        for (int _k = 0; _k < 4; _k++) {                                     \
            int _f4  = tid + _k * 256;                                       \
            int _row = _f4 >> 5, _col = _f4 & 31;                            \
            int _sr  = min(_ts + _row, n1 - 1);                              \
            const float4* _src = kb4 + (size_t)_sr * 32 + _col;              \
            unsigned int _dst = sbase + (unsigned int)((BUFI)*(TILE*32)      \
                              + _row*32 + (_col ^ (_row & 7))) * 16u;        \
            asm volatile("cp.async.cg.shared.global [%0], [%1], 16;\n"       \
                         :: "r"(_dst), "l"(_src));                           \
        }                                                                    \
        asm volatile("cp.async.commit_group;\n");                            \
    } while (0)

    while (g < hi) {
        while (g >= sP[b + 1]) b++;                 // locate batch (ascending)
        const int segEnd = min(hi, sP[b + 1]);
        const int n0 = g - sP[b];
        const int n1 = segEnd - sP[b];
        const bool uniform = (((b & 1) ? suO : suE) >> (b >> 1)) & 1u;
        const int T = (n1 - n0 + TILE - 1) / TILE;

        const float4* kb4 = (const float4*)(kb + (size_t)b * N_ * D_);

        ISSUE_TILE(0, 0);                           // independent of q

        // wait for q of this batch (counter >= PRODB; cumulative across
        // replays -> instant pass later, benign: identical data rewritten)
        while (*((volatile int*)&g_qcnt[b]) < PRODB) __nanosleep(64);
        __threadfence();
        // stage q/qa for this batch into smem (phase 1 reads them broadcast)
        if (tid < D_)            sq [tid]       = g_q [b*D_ + tid];
        else if (tid < 2*D_)     sqa[tid - D_]  = g_qa[b*D_ + tid - D_];

        float  s = 0.f;
        float4 acc = make_float4(0.f, 0.f, 0.f, 0.f);

        for (int t = 0; t < T; t++) {
            asm volatile("cp.async.wait_group 0;\n" ::: "memory");
            __syncthreads();   // tile t + w[t-1] + sq/sqa visible to all

            // ---- phase 2 of tile t-1 (all 8 warps, 4 slots each) ----
            if (t > 0) {
                const float4* pbuf = sbuf[(t-1) & 1];
                const float*  pw   = wbuf[(t-1) & 1];
                #pragma unroll
                for (int r = 0; r < 4; r++) {
                    const int sl = warp*4 + r;
                    float  ws = pw[sl];                       // broadcast
                    float4 k  = pbuf[sl*32 + (lane ^ (sl & 7))];  // col=lane
                    s += ws;
                    acc.x += ws*k.x; acc.y += ws*k.y;
                    acc.z += ws*k.z; acc.w += ws*k.w;
                }
            }
            __syncthreads();                  // buf[(t-1)&1] free, wbuf consumed

            if (t + 1 < T) ISSUE_TILE(t + 1, (t + 1) & 1);

            // ---- phase 1 of tile t (rotating warp; thread-per-slot) ----
            if (warp == (t & 7)) {
                const float4* buf = sbuf[t & 1];
                float dot = 0.f, nrm = 0.f;
                #pragma unroll 8
                for (int i = 0; i < 32; i++) {
                    float4 k  = buf[lane*32 + (i ^ (lane & 7))];  // col=i
                    float4 qv = *(const float4*)&sq [i*4];        // broadcast
                    float4 qa = *(const float4*)&sqa[i*4];
                    float ix = k.x*qv.x, iy = k.y*qv.y;
                    float iz = k.z*qv.z, iw = k.w*qv.w;
                    nrm += ix*ix + iy*iy + iz*iz + iw*iw;
                    dot += k.x*qa.x + k.y*qa.y + k.z*qa.z + k.w*qa.w;
                }
                float L = uniform ? 0.f : (dot * rsqrtf(fmaxf(nrm, 1e-24f)) + ba);
                const int slot = n0 + t*TILE + lane;
                wbuf[t & 1][lane] = (slot < n1) ? __expf(L - M) : 0.f;
            }
        }
        // epilogue: phase 2 of the last tile
        __syncthreads();
        {
            const float4* pbuf = sbuf[(T-1) & 1];
            const float*  pw   = wbuf[(T-1) & 1];
            #pragma unroll
            for (int r = 0; r < 4; r++) {
                const int sl = warp*4 + r;
                float  ws = pw[sl];
                float4 k  = pbuf[sl*32 + (lane ^ (sl & 7))];
                s += ws;
                acc.x += ws*k.x; acc.y += ws*k.y;
                acc.z += ws*k.z; acc.w += ws*k.w;
            }
        }

        // flush this segment's partial to (bid, b): reduce 8 warps
        *(float4*)&sacc[warp][lane*4] = acc;
        if (lane == 0) ssum[warp] = s;        // NOTE: s differs per lane? no:
        __syncthreads();                      // every lane added same ws set
        if (tid < D_) {
            float a = 0.f;
            #pragma unroll
            for (int j = 0; j < 8; j++) a += sacc[j][tid];
            g_part_acc[((size_t)bid*B_ + b)*D_ + tid] = a;
        } else if (tid == D_) {
            float t2 = 0.f;
            #pragma unroll
            for (int j = 0; j < 8; j++) t2 += ssum[j];
            g_part_s[bid*B_ + b] = t2;
        }
        __syncthreads();                      // sacc/sq reuse across segments
        g = segEnd;
    }
    #undef ISSUE_TILE

    // ---- ticket; last 64 ticket-takers combine one batch each ----
    __threadfence();
    __syncthreads();
    if (tid == 0) sticket = atomicAdd(&g_fin, 1);     // cumulative
    __syncthreads();
    const int pos  = sticket % G_;
    const int tbase = sticket - pos;
    if (pos >= G_ - B_) {
        const int cb = pos - (G_ - B_);               // batch to combine
        if (tid == 0) {                               // wait for all G_ blocks
            while (*((volatile int*)&g_fin) < tbase + G_) __nanosleep(64);
        }
        __syncthreads();
        __threadfence();
        const int Pb  = sP[cb], Pb1 = sP[cb + 1];
        // contributing blocks: ranges intersecting [Pb, Pb1)
        int j0 = (int)(((long long)(Pb + 1) * G_ + W - 1) / W) - 1;
        int j1 = (int)(((long long)Pb1 * G_ - 1) / W);
        if (j0 < 0) j0 = 0;
        if (j1 > G_ - 1) j1 = G_ - 1;
        if (tid < D_) {
            float av = 0.f, ss = 0.f;
            for (int j = j0; j <= j1; j++) {
                const int sj = (int)((long long)j       * W / G_);
                const int ej = (int)((long long)(j + 1) * W / G_);
                if (sj == ej) continue;               // empty block wrote nothing
                av += __ldcg(&g_part_acc[((size_t)j*B_ + cb)*D_ + tid]);
                ss += __ldcg(&g_part_s[j*B_ + cb]);
            }
            out[cb*D_ + tid] = av / ss;               // ss > 0 (>=1 slot, w>0)
        }
    }
}

extern "C" void kernel_launch(void* const* d_in, const int* in_sizes, int n_in,
                              void* d_out, int out_size)
{
    const float* kb  = (const float*)d_in[0];
    const float* vq  = (const float*)d_in[1];
    const int*   ion = (const int*)  d_in[2];   // int32 or int64, auto-detected
    const float* Wq  = (const float*)d_in[3];
    const float* bq  = (const float*)d_in[4];
    const float* Wa  = (const float*)d_in[5];
    const float* ba  = (const float*)d_in[6];
    float* out = (float*)d_out;

    fused_kernel<<<G_, 256>>>(kb, vq, ion, Wq, bq, Wa, ba, out);
}

// round 14
// speedup vs baseline: 1.4747x; 1.4747x over previous
#include <cuda_runtime.h>
#include <cstdint>
#include <math.h>

#define B_    64
#define N_    4096
#define D_    128
#define E_    512
#define S_    16                // N-splits per batch -> att grid 1024
#define GPB   32                // 8-lane groups per att block
#define TSTREAMS (S_*GPB)       // 512 interleaved slot streams per batch
#define GRID2 (B_*S_)           // 1024

// ---- device scratch (no allocations; 16B-aligned for float4 access) ----
// Replay-safe: g_fin is a cumulative monotonic counter (mod-GRID2 test);
// data arrays are rewritten with identical values each replay before reads.
__device__ __align__(16) float g_q  [B_*D_];
__device__ __align__(16) float g_qa [B_*D_];
__device__ __align__(16) float g_pacc[B_*S_*D_];
__device__ float g_ps [B_*S_];
__device__ int   g_fin;

// ============================================================
// Kernel 1: proj_q = vecQ @ Wq^T + bq ; qa = q * Wa.
// Warp computes 4 outputs of one batch (shared v regs, 20 indep
// float4 loads in flight). grid 256 x 8 warps = 2048 warps.
// ============================================================
__global__ void __launch_bounds__(256)
proj_kernel(const float* __restrict__ vq,
            const float* __restrict__ Wq,
            const float* __restrict__ bq,
            const float* __restrict__ Wa)
{
    const int warp = threadIdx.x >> 5;
    const int lane = threadIdx.x & 31;
    const int wg   = blockIdx.x * 8 + warp;    // 0..2047
    const int b    = wg >> 5;                  // batch
    const int d0   = (wg & 31) * 4;            // 4 outputs d0..d0+3

    const float4* v4 = (const float4*)(vq + (size_t)b * E_);
    float4 v[4];
    #pragma unroll
    for (int j = 0; j < 4; j++) v[j] = v4[j*32 + lane];

    float a[4];
    #pragma unroll
    for (int t = 0; t < 4; t++) {
        const float4* w4 = (const float4*)(Wq + (size_t)(d0 + t) * E_);
        float acc = 0.f;
        #pragma unroll
        for (int j = 0; j < 4; j++) {
            float4 y = w4[j*32 + lane];
            acc += v[j].x*y.x + v[j].y*y.y + v[j].z*y.z + v[j].w*y.w;
        }
        a[t] = acc;
    }
    #pragma unroll
    for (int t = 0; t < 4; t++) {
        #pragma unroll
        for (int off = 16; off > 0; off >>= 1)
            a[t] += __shfl_xor_sync(0xffffffffu, a[t], off);
    }
    if (lane < 4) {
        const int d = d0 + lane;
        float qv = __shfl_sync(0xffffffffu, a[lane], 0) ;
        // a[lane] already fully reduced in every lane; take own value
        qv = a[lane] + bq[d];
        g_q [b*D_ + d] = qv;
        g_qa[b*D_ + d] = qv * Wa[d];
    }
}

// ============================================================
// Kernel 2: att pass (R4-proven hot loop) + fused ticket combine.
// grid 1024 (multi-wave: natural load balancing), 256 threads,
// 8-lane groups, 2-slot batching, __ldcs streaming loads,
// fixed-reference weights w = exp(L - M), M = max(ba+||Wa||,0).
// ============================================================
__global__ void __launch_bounds__(256)
att_kernel(const float* __restrict__ kb,
           const int*   __restrict__ ion,
           const float* __restrict__ Wa,
           const float* __restrict__ ba_p,
           float*       __restrict__ out)
{
    const int tid   = threadIdx.x;
    const int warp  = tid >> 5, lane = tid & 31;
    const int bs    = blockIdx.x;
    const int b     = bs >> 4;          // / S_
    const int split = bs & (S_ - 1);
    const int g     = lane >> 3, sub = lane & 7;
    const int gid   = warp * 4 + g;     // 0..31

    __shared__ int   scnt;
    __shared__ float sM, sba;
    __shared__ __align__(16) float sacc[GPB][132];
    __shared__ float ssum[GPB];
    __shared__ int   sticket;

    // ---- per-block meta ----
    if (warp == 0) {
        // int64 vs int32 decode: values in [0,4096); if int64 (LE) every odd
        // 32-bit word of the first 64 is 0. Detection reads stay in first
        // 256B; word 2*b (<=508B) read only when layout is int64 (512B alloc).
        bool oz   = (ion[2*lane + 1] == 0);
        bool is64 = __all_sync(0xffffffffu, oz);
        if (lane == 0) scnt = is64 ? ion[2*b] : ion[b];
    } else if (warp == 1) {
        // M = max(ba + ||Wa||, 0) >= every logit (Cauchy-Schwarz)
        float t = 0.f;
        #pragma unroll
        for (int i = 0; i < 4; i++) { float wv = Wa[i*32 + lane]; t += wv*wv; }
        #pragma unroll
        for (int off = 16; off > 0; off >>= 1)
            t += __shfl_xor_sync(0xffffffffu, t, off);
        if (lane == 0) { float ba = *ba_p; sba = ba; sM = fmaxf(ba + sqrtf(t), 0.f); }
    }
    __syncthreads();

    const int   cnt     = scnt;
    const int   limit   = (cnt == 0) ? N_ : cnt;
    const bool  uniform = (cnt == 0);
    const float M  = sM;
    const float ba = sba;

    // q,qa: this lane's 16 floats (elements i*32 + sub*4 .. +3)
    float4 q[4], qa[4];
    #pragma unroll
    for (int i = 0; i < 4; i++) {
        q[i]  = ((const float4*)(g_q  + b*D_))[i*8 + sub];
        qa[i] = ((const float4*)(g_qa + b*D_))[i*8 + sub];
    }

    const float4* kb4 = (const float4*)(kb + (size_t)b * N_ * D_);

    float  s = 0.f;
    float4 acc[4] = {make_float4(0,0,0,0), make_float4(0,0,0,0),
                     make_float4(0,0,0,0), make_float4(0,0,0,0)};
    const float4 ZERO = make_float4(0,0,0,0);

    // two slots per group per iteration for MLP (8 float4 in flight/thread)
    for (int n0 = split*GPB + gid; __any_sync(0xffffffffu, n0 < limit);
         n0 += 2*TSTREAMS) {
        const int  n1 = n0 + TSTREAMS;
        const bool v0 = n0 < limit;
        const bool v1 = n1 < limit;

        float4 k0[4], k1[4];
        #pragma unroll
        for (int i = 0; i < 4; i++)
            k0[i] = v0 ? __ldcs(&kb4[(size_t)n0*32 + i*8 + sub]) : ZERO;
        #pragma unroll
        for (int i = 0; i < 4; i++)
            k1[i] = v1 ? __ldcs(&kb4[(size_t)n1*32 + i*8 + sub]) : ZERO;

        #pragma unroll
        for (int t = 0; t < 2; t++) {
            float4* k = t ? k1 : k0;
            const bool v = t ? v1 : v0;
            float dot = 0.f, nrm = 0.f;
            #pragma unroll
            for (int i = 0; i < 4; i++) {
                float px = k[i].x*q[i].x, py = k[i].y*q[i].y;
                float pz = k[i].z*q[i].z, pw = k[i].w*q[i].w;
                nrm += px*px + py*py + pz*pz + pw*pw;
                dot += k[i].x*qa[i].x + k[i].y*qa[i].y
                     + k[i].z*qa[i].z + k[i].w*qa[i].w;
            }
            #pragma unroll
            for (int off = 4; off > 0; off >>= 1) {   // 8-lane reduce
                dot += __shfl_xor_sync(0xffffffffu, dot, off);
                nrm += __shfl_xor_sync(0xffffffffu, nrm, off);
            }
            float L = uniform ? 0.f : (dot * rsqrtf(fmaxf(nrm, 1e-24f)) + ba);
            float w = v ? __expf(L - M) : 0.f;    // L <= M: never overflows
            s += w;
            #pragma unroll
            for (int i = 0; i < 4; i++) {
                acc[i].x += w * k[i].x;  acc[i].y += w * k[i].y;
                acc[i].z += w * k[i].z;  acc[i].w += w * k[i].w;
            }
        }
    }

    // merge 32 groups of this CTA (132-stride: aligned, conflict-free)
    #pragma unroll
    for (int i = 0; i < 4; i++)
        *(float4*)&sacc[gid][i*32 + sub*4] = acc[i];
    if (sub == 0) ssum[gid] = s;
    __syncthreads();

    if (tid < D_) {
        float a = 0.f;
        #pragma unroll
        for (int j = 0; j < GPB; j++) a += sacc[j][tid];
        g_pacc[bs*D_ + tid] = a;
    } else if (tid == D_) {
        float t = 0.f;
        #pragma unroll
        for (int j = 0; j < GPB; j++) t += ssum[j];
        g_ps[bs] = t;
    }

    // ---- ticket; last 64 ticket-takers combine one batch each ----
    __threadfence();
    __syncthreads();
    if (tid == 0) sticket = atomicAdd(&g_fin, 1);     // cumulative
    __syncthreads();
    const int pos   = sticket % GRID2;
    const int tbase = sticket - pos;
    if (pos >= GRID2 - B_) {
        const int cb = pos - (GRID2 - B_);            // batch to combine
        if (tid == 0) {                               // wait for all blocks
            while (*((volatile int*)&g_fin) < tbase + GRID2) __nanosleep(64);
        }
        __syncthreads();
        __threadfence();
        if (tid < D_) {
            float ss = 0.f, av = 0.f;
            #pragma unroll
            for (int i = 0; i < S_; i++) {
                ss += __ldcg(&g_ps[cb*S_ + i]);
                av += __ldcg(&g_pacc[(cb*S_ + i)*D_ + tid]);
            }
            out[cb*D_ + tid] = av / ss;               // ss > 0 (limit >= 1)
        }
    }
}

extern "C" void kernel_launch(void* const* d_in, const int* in_sizes, int n_in,
                              void* d_out, int out_size)
{
    const float* kb  = (const float*)d_in[0];
    const float* vq  = (const float*)d_in[1];
    const int*   ion = (const int*)  d_in[2];   // int32 or int64, auto-detected
    const float* Wq  = (const float*)d_in[3];
    const float* bq  = (const float*)d_in[4];
    const float* Wa  = (const float*)d_in[5];
    const float* ba  = (const float*)d_in[6];
    float* out = (float*)d_out;

    proj_kernel<<<256,   256>>>(vq, Wq, bq, Wa);
    att_kernel <<<GRID2, 256>>>(kb, ion, Wa, ba, out);
}

// round 15
// speedup vs baseline: 1.5149x; 1.0272x over previous
#include <cuda_runtime.h>
#include <cstdint>
#include <math.h>

#define B_    64
#define N_    4096
#define D_    128
#define E_    512
#define S_    16                // N-splits per batch -> att grid 1024
#define GPB   32                // 8-lane groups per att block
#define TSTREAMS (S_*GPB)       // 512 interleaved slot streams per batch
#define GRID2 (B_*S_)           // 1024

typedef unsigned long long u64;

// ---- packed f32x2 helpers (sm_103a FFMA2 pipe) ----
__device__ __forceinline__ u64 f2mul(u64 a, u64 b) {
    u64 r; asm("mul.rn.f32x2 %0, %1, %2;" : "=l"(r) : "l"(a), "l"(b)); return r;
}
__device__ __forceinline__ u64 f2fma(u64 a, u64 b, u64 c) {
    u64 r; asm("fma.rn.f32x2 %0, %1, %2, %3;" : "=l"(r) : "l"(a), "l"(b), "l"(c)); return r;
}
__device__ __forceinline__ float f2hadd(u64 v) {
    float lo, hi; asm("mov.b64 {%0,%1}, %2;" : "=f"(lo), "=f"(hi) : "l"(v));
    return lo + hi;
}
__device__ __forceinline__ u64 f2pack(float x) {
    u64 r; asm("mov.b64 %0, {%1,%1};" : "=l"(r) : "f"(x)); return r;
}

// ---- device scratch (no allocations; 16B-aligned for vector access) ----
// Replay-safe: g_fin is a cumulative monotonic counter (mod-GRID2 test);
// data arrays are rewritten with identical values each replay before reads.
__device__ __align__(16) float g_q  [B_*D_];
__device__ __align__(16) float g_qa [B_*D_];
__device__ __align__(16) float g_pacc[B_*S_*D_];
__device__ float g_ps [B_*S_];
__device__ int   g_fin;

// ============================================================
// Kernel 1: proj_q = vecQ @ Wq^T + bq ; qa = q * Wa.
// Warp computes 4 outputs of one batch (shared v regs, 20 indep
// float4 loads in flight). grid 256 x 8 warps = 2048 warps.
// ============================================================
__global__ void __launch_bounds__(256)
proj_kernel(const float* __restrict__ vq,
            const float* __restrict__ Wq,
            const float* __restrict__ bq,
            const float* __restrict__ Wa)
{
    const int warp = threadIdx.x >> 5;
    const int lane = threadIdx.x & 31;
    const int wg   = blockIdx.x * 8 + warp;    // 0..2047
    const int b    = wg >> 5;                  // batch
    const int d0   = (wg & 31) * 4;            // 4 outputs d0..d0+3

    const float4* v4 = (const float4*)(vq + (size_t)b * E_);
    float4 v[4];
    #pragma unroll
    for (int j = 0; j < 4; j++) v[j] = v4[j*32 + lane];

    float a[4];
    #pragma unroll
    for (int t = 0; t < 4; t++) {
        const float4* w4 = (const float4*)(Wq + (size_t)(d0 + t) * E_);
        float acc = 0.f;
        #pragma unroll
        for (int j = 0; j < 4; j++) {
            float4 y = w4[j*32 + lane];
            acc += v[j].x*y.x + v[j].y*y.y + v[j].z*y.z + v[j].w*y.w;
        }
        a[t] = acc;
    }
    #pragma unroll
    for (int t = 0; t < 4; t++) {
        #pragma unroll
        for (int off = 16; off > 0; off >>= 1)
            a[t] += __shfl_xor_sync(0xffffffffu, a[t], off);
    }
    if (lane < 4) {
        const int d = d0 + lane;
        float qv = a[lane] + bq[d];        // fully reduced in every lane
        g_q [b*D_ + d] = qv;
        g_qa[b*D_ + d] = qv * Wa[d];
    }
}

// ============================================================
// Kernel 2: att pass with packed-f32x2 math + fused ticket combine.
// grid 1024 (multi-wave: natural load balancing), 256 threads,
// 8-lane groups, 2-slot batching, __ldcg loads (L2-persisting),
// fixed-reference weights w = exp(L - M), M = max(ba+||Wa||,0).
// ============================================================
__global__ void __launch_bounds__(256)
att_kernel(const float* __restrict__ kb,
           const int*   __restrict__ ion,
           const float* __restrict__ Wa,
           const float* __restrict__ ba_p,
           float*       __restrict__ out)
{
    const int tid   = threadIdx.x;
    const int warp  = tid >> 5, lane = tid & 31;
    const int bs    = blockIdx.x;
    const int b     = bs >> 4;          // / S_
    const int split = bs & (S_ - 1);
    const int g     = lane >> 3, sub = lane & 7;
    const int gid   = warp * 4 + g;     // 0..31

    __shared__ int   scnt;
    __shared__ float sM, sba;
    __shared__ __align__(16) float sacc[GPB][132];
    __shared__ float ssum[GPB];
    __shared__ int   sticket;

    // ---- per-block meta ----
    if (warp == 0) {
        // int64 vs int32 decode: values in [0,4096); if int64 (LE) every odd
        // 32-bit word of the first 64 is 0. Detection reads stay in first
        // 256B; word 2*b (<=508B) read only when layout is int64 (512B alloc).
        bool oz   = (ion[2*lane + 1] == 0);
        bool is64 = __all_sync(0xffffffffu, oz);
        if (lane == 0) scnt = is64 ? ion[2*b] : ion[b];
    } else if (warp == 1) {
        // M = max(ba + ||Wa||, 0) >= every logit (Cauchy-Schwarz)
        float t = 0.f;
        #pragma unroll
        for (int i = 0; i < 4; i++) { float wv = Wa[i*32 + lane]; t += wv*wv; }
        #pragma unroll
        for (int off = 16; off > 0; off >>= 1)
            t += __shfl_xor_sync(0xffffffffu, t, off);
        if (lane == 0) { float ba = *ba_p; sba = ba; sM = fmaxf(ba + sqrtf(t), 0.f); }
    }
    __syncthreads();

    const int   cnt     = scnt;
    const int   limit   = (cnt == 0) ? N_ : cnt;
    const bool  uniform = (cnt == 0);
    const float M  = sM;
    const float ba = sba;

    // q,qa: this lane's 16 floats (elements i*32 + sub*4 .. +3), packed f32x2
    ulonglong2 q2[4], qa2[4];
    #pragma unroll
    for (int i = 0; i < 4; i++) {
        q2[i]  = ((const ulonglong2*)(g_q  + b*D_))[i*8 + sub];
        qa2[i] = ((const ulonglong2*)(g_qa + b*D_))[i*8 + sub];
    }

    const ulonglong2* kb2 = (const ulonglong2*)(kb + (size_t)b * N_ * D_);

    float s = 0.f;
    ulonglong2 acc2[4];
    #pragma unroll
    for (int i = 0; i < 4; i++) { acc2[i].x = 0ull; acc2[i].y = 0ull; }

    // two slots per group per iteration (8 x 16B loads in flight/thread);
    // out-of-range slots clamp to limit-1 and are annihilated by w=0.
    for (int n0 = split*GPB + gid; __any_sync(0xffffffffu, n0 < limit);
         n0 += 2*TSTREAMS) {
        const int  n1 = n0 + TSTREAMS;
        const bool v0 = n0 < limit;
        const bool v1 = n1 < limit;
        const int  m0 = min(n0, limit - 1);
        const int  m1 = min(n1, limit - 1);

        ulonglong2 k0[4], k1[4];
        #pragma unroll
        for (int i = 0; i < 4; i++)
            k0[i] = __ldcg(&kb2[(size_t)m0*32 + i*8 + sub]);
        #pragma unroll
        for (int i = 0; i < 4; i++)
            k1[i] = __ldcg(&kb2[(size_t)m1*32 + i*8 + sub]);

        #pragma unroll
        for (int t = 0; t < 2; t++) {
            ulonglong2* k = t ? k1 : k0;
            const bool v = t ? v1 : v0;
            u64 dot2 = 0ull, nrm2 = 0ull;
            #pragma unroll
            for (int i = 0; i < 4; i++) {
                u64 ipx = f2mul(k[i].x, q2[i].x);
                u64 ipy = f2mul(k[i].y, q2[i].y);
                nrm2 = f2fma(ipx, ipx, nrm2);
                nrm2 = f2fma(ipy, ipy, nrm2);
                dot2 = f2fma(k[i].x, qa2[i].x, dot2);
                dot2 = f2fma(k[i].y, qa2[i].y, dot2);
            }
            float dot = f2hadd(dot2);
            float nrm = f2hadd(nrm2);
            #pragma unroll
            for (int off = 4; off > 0; off >>= 1) {   // 8-lane reduce
                dot += __shfl_xor_sync(0xffffffffu, dot, off);
                nrm += __shfl_xor_sync(0xffffffffu, nrm, off);
            }
            float L = uniform ? 0.f : (dot * rsqrtf(fmaxf(nrm, 1e-24f)) + ba);
            float w = v ? __expf(L - M) : 0.f;    // L <= M: never overflows
            s += w;
            u64 ww = f2pack(w);
            #pragma unroll
            for (int i = 0; i < 4; i++) {
                acc2[i].x = f2fma(k[i].x, ww, acc2[i].x);
                acc2[i].y = f2fma(k[i].y, ww, acc2[i].y);
            }
        }
    }

    // merge 32 groups of this CTA (132-stride: aligned, conflict-free)
    #pragma unroll
    for (int i = 0; i < 4; i++)
        *(ulonglong2*)&sacc[gid][i*32 + sub*4] = acc2[i];
    if (sub == 0) ssum[gid] = s;
    __syncthreads();

    if (tid < D_) {
        float a = 0.f;
        #pragma unroll
        for (int j = 0; j < GPB; j++) a += sacc[j][tid];
        g_pacc[bs*D_ + tid] = a;
    } else if (tid == D_) {
        float t = 0.f;
        #pragma unroll
        for (int j = 0; j < GPB; j++) t += ssum[j];
        g_ps[bs] = t;
    }

    // ---- ticket; last 64 ticket-takers combine one batch each ----
    __threadfence();
    __syncthreads();
    if (tid == 0) sticket = atomicAdd(&g_fin, 1);     // cumulative
    __syncthreads();
    const int pos   = sticket % GRID2;
    const int tbase = sticket - pos;
    if (pos >= GRID2 - B_) {
        const int cb = pos - (GRID2 - B_);            // batch to combine
        if (tid == 0) {                               // wait for all blocks
            while (*((volatile int*)&g_fin) < tbase + GRID2) __nanosleep(64);
        }
        __syncthreads();
        __threadfence();
        if (tid < D_) {
            float ss = 0.f, av = 0.f;
            #pragma unroll
            for (int i = 0; i < S_; i++) {
                ss += __ldcg(&g_ps[cb*S_ + i]);
                av += __ldcg(&g_pacc[(cb*S_ + i)*D_ + tid]);
            }
            out[cb*D_ + tid] = av / ss;               // ss > 0 (limit >= 1)
        }
    }
}

extern "C" void kernel_launch(void* const* d_in, const int* in_sizes, int n_in,
                              void* d_out, int out_size)
{
    const float* kb  = (const float*)d_in[0];
    const float* vq  = (const float*)d_in[1];
    const int*   ion = (const int*)  d_in[2];   // int32 or int64, auto-detected
    const float* Wq  = (const float*)d_in[3];
    const float* bq  = (const float*)d_in[4];
    const float* Wa  = (const float*)d_in[5];
    const float* ba  = (const float*)d_in[6];
    float* out = (float*)d_out;

    proj_kernel<<<256,   256>>>(vq, Wq, bq, Wa);
    att_kernel <<<GRID2, 256>>>(kb, ion, Wa, ba, out);
}